// round 1
// baseline (speedup 1.0000x reference)
#include <cuda_runtime.h>
#include <math.h>

// Shapes
//   amplitudes, frequencies : [8, 250, 100] f32
//   out = concat( amp_env [8, 64000, 100], freq_env [8, 250, 100] )  f32
#define B            8
#define FRAMES       250
#define CH           100
#define CTRL_ELEMS   (B * FRAMES * CH)        // 200000
#define T_OUT        64000
#define HOP          256                       // 64000 / 250
#define ENV_ELEMS    (B * T_OUT * CH)          // 51200000
#define ENV_VEC4     (ENV_ELEMS / 4)           // 12800000

// Scratch for scaled+nyquist-masked amplitudes (no cudaMalloc allowed).
__device__ __align__(16) float g_amps[CTRL_ELEMS];

// ---------------------------------------------------------------------------
// Kernel 1: get_controls — amp scaling, freq sigmoid mapping, nyquist mask.
// Writes freqs directly into the tail of d_out, masked amps into g_amps.
// ---------------------------------------------------------------------------
__global__ void controls_kernel(const float* __restrict__ amp_in,
                                const float* __restrict__ freq_in,
                                float* __restrict__ freq_out) {
    int idx = blockIdx.x * blockDim.x + threadIdx.x;
    if (idx >= CTRL_ELEMS) return;

    const float LOG10_F   = 2.302585092994046f;   // ln(10)
    const float MIDI_MAX  = 119.21309485364912f;  // 12*(log2 8000 - log2 440) + 69
    const float NYQ       = 22050.0f;             // SR / 2

    // frequencies_sigmoid
    float f  = freq_in[idx];
    float uf = 1.0f / (1.0f + expf(-f));
    float freq = 440.0f * exp2f((uf * MIDI_MAX - 69.0f) * (1.0f / 12.0f));

    // scale_function: 2 * sigmoid(a)^ln(10) + 1e-7
    float a  = amp_in[idx];
    float sa = 1.0f / (1.0f + expf(-a));
    float amp = 2.0f * powf(sa, LOG10_F) + 1e-7f;

    // remove_above_nyquist: harmonic index = (idx % 100) + 1
    int k = idx - (idx / CH) * CH;            // channel index 0..99
    float h = (float)(k + 1);
    float aa = ((freq * h < NYQ) ? 1.0f : 0.0f) + 1e-4f;

    g_amps[idx]  = amp * aa;
    freq_out[idx] = freq;
}

// ---------------------------------------------------------------------------
// Kernel 2: upsample_with_windows, reduced to a 2-tap hann crossfade.
//   seg = global frame row >> 8 encodes (b, j) directly since T_OUT = 250*256.
//   out[row, c] = amps[seg, c]*(1-w) + amps[seg_next, c]*w,
//   w = 0.5*(1 - cos(pi * r / 256)), r = row & 255.
//   seg_next clamps at the last frame of each batch (x[:, -1:] duplication).
// Vectorized: each thread produces one float4 (CH=100 is a multiple of 4, so
// an aligned float4 never crosses a row boundary).
// ---------------------------------------------------------------------------
__global__ void upsample_kernel(float* __restrict__ out) {
    unsigned i = blockIdx.x * blockDim.x + threadIdx.x;   // float4 index
    if (i >= ENV_VEC4) return;

    unsigned e   = i * 4u;               // flat element index
    unsigned row = e / 100u;             // global (b*T_OUT + t) row
    unsigned c   = e - row * 100u;       // channel (multiple of 4)

    unsigned seg = row >> 8;             // = b*250 + j
    unsigned r   = row & 255u;
    unsigned segn = seg + 1u;
    if (segn % 250u == 0u) segn = seg;   // clamp: frame 250 == frame 249

    float w  = 0.5f - 0.5f * cospif((float)r * (1.0f / 256.0f));
    float wm = 1.0f - w;

    float4 x0 = *reinterpret_cast<const float4*>(&g_amps[seg  * 100u + c]);
    float4 x1 = *reinterpret_cast<const float4*>(&g_amps[segn * 100u + c]);

    float4 o;
    o.x = x0.x * wm + x1.x * w;
    o.y = x0.y * wm + x1.y * w;
    o.z = x0.z * wm + x1.z * w;
    o.w = x0.w * wm + x1.w * w;

    reinterpret_cast<float4*>(out)[i] = o;
}

// ---------------------------------------------------------------------------
extern "C" void kernel_launch(void* const* d_in, const int* in_sizes, int n_in,
                              void* d_out, int out_size) {
    const float* amps  = (const float*)d_in[0];
    const float* freqs = (const float*)d_in[1];
    float* out = (float*)d_out;

    controls_kernel<<<(CTRL_ELEMS + 255) / 256, 256>>>(amps, freqs,
                                                       out + ENV_ELEMS);
    upsample_kernel<<<(ENV_VEC4 + 255) / 256, 256>>>(out);
}

// round 2
// speedup vs baseline: 1.2964x; 1.2964x over previous
#include <cuda_runtime.h>
#include <math.h>

// Shapes
//   amplitudes, frequencies : [8, 250, 100] f32
//   out = concat( amp_env [8, 64000, 100], freq_env [8, 250, 100] )  f32
#define B            8
#define FRAMES       250
#define CH           100
#define CTRL_ELEMS   (B * FRAMES * CH)        // 200000
#define T_OUT        64000
#define HOP          256                      // 64000 / 250
#define ENV_ELEMS    (B * T_OUT * CH)         // 51200000
#define SEGS         (B * FRAMES)             // 2000 segments
#define SEG_VEC4     (HOP * (CH / 4))         // 6400 float4 per segment
#define UP_THREADS   800                      // 32 rows x 25 float4-groups

// Scratch for scaled+nyquist-masked amplitudes (no cudaMalloc allowed).
__device__ __align__(16) float g_amps[CTRL_ELEMS];

// ---------------------------------------------------------------------------
// Kernel 1: get_controls — amp scaling, freq sigmoid mapping, nyquist mask.
// Writes freqs directly into the tail of d_out, masked amps into g_amps.
// ---------------------------------------------------------------------------
__global__ void controls_kernel(const float* __restrict__ amp_in,
                                const float* __restrict__ freq_in,
                                float* __restrict__ freq_out) {
    int idx = blockIdx.x * blockDim.x + threadIdx.x;
    if (idx >= CTRL_ELEMS) return;

    const float LOG10_F   = 2.302585092994046f;   // ln(10)
    const float MIDI_MAX  = 119.21309485364912f;  // 12*(log2 8000 - log2 440) + 69
    const float NYQ       = 22050.0f;             // SR / 2

    // frequencies_sigmoid
    float f  = freq_in[idx];
    float uf = 1.0f / (1.0f + expf(-f));
    float freq = 440.0f * exp2f((uf * MIDI_MAX - 69.0f) * (1.0f / 12.0f));

    // scale_function: 2 * sigmoid(a)^ln(10) + 1e-7
    float a  = amp_in[idx];
    float sa = 1.0f / (1.0f + expf(-a));
    float amp = 2.0f * powf(sa, LOG10_F) + 1e-7f;

    // remove_above_nyquist: harmonic index = (idx % 100) + 1
    int k = idx - (idx / CH) * CH;            // channel index 0..99
    float h = (float)(k + 1);
    float aa = ((freq * h < NYQ) ? 1.0f : 0.0f) + 1e-4f;

    g_amps[idx]  = amp * aa;
    freq_out[idx] = freq;
}

// ---------------------------------------------------------------------------
// Kernel 2: upsample_with_windows as a register-resident 2-tap crossfade.
//
// One block per segment (b, j). Thread tid owns a fixed channel float4-group
// c4 = tid % 25 and base row r0 = tid / 25; endpoints x0 = amps[seg][c4],
// x1 = amps[segn][c4] are loaded ONCE, d = x1 - x0 precomputed, then the
// thread emits 8 stores at rows r0 + 32k:
//     out[row] = x0 + d * w[row],   w[r] = 0.5 - 0.5*cospi(r/256)
// Stores are fully coalesced: iteration k writes float4 indices
// seg*6400 + 800k + tid (contiguous across the block).
// ---------------------------------------------------------------------------
__global__ __launch_bounds__(UP_THREADS) void upsample_kernel(
        float4* __restrict__ out) {
    __shared__ float sw[HOP];

    const int tid = threadIdx.x;
    const int seg = blockIdx.x;

    if (tid < HOP) {
        sw[tid] = 0.5f - 0.5f * cospif((float)tid * (1.0f / 256.0f));
    }

    int segn = seg + 1;
    if (segn % FRAMES == 0) segn = seg;       // clamp: frame 250 == frame 249

    const int c4 = tid % 25;                  // channel float4-group (fixed)
    const int r0 = tid / 25;                  // base row within segment

    __syncthreads();

    const float4 x0 = *reinterpret_cast<const float4*>(&g_amps[seg  * CH + c4 * 4]);
    const float4 x1 = *reinterpret_cast<const float4*>(&g_amps[segn * CH + c4 * 4]);
    float4 d;
    d.x = x1.x - x0.x;
    d.y = x1.y - x0.y;
    d.z = x1.z - x0.z;
    d.w = x1.w - x0.w;

    float4* o = out + (size_t)seg * SEG_VEC4 + tid;

#pragma unroll
    for (int k = 0; k < 8; k++) {
        const float w = sw[r0 + 32 * k];
        float4 v;
        v.x = fmaf(d.x, w, x0.x);
        v.y = fmaf(d.y, w, x0.y);
        v.z = fmaf(d.z, w, x0.z);
        v.w = fmaf(d.w, w, x0.w);
        o[UP_THREADS * k] = v;
    }
}

// ---------------------------------------------------------------------------
extern "C" void kernel_launch(void* const* d_in, const int* in_sizes, int n_in,
                              void* d_out, int out_size) {
    const float* amps  = (const float*)d_in[0];
    const float* freqs = (const float*)d_in[1];
    float* out = (float*)d_out;

    controls_kernel<<<(CTRL_ELEMS + 255) / 256, 256>>>(amps, freqs,
                                                       out + ENV_ELEMS);
    upsample_kernel<<<SEGS, UP_THREADS>>>((float4*)out);
}

// round 3
// speedup vs baseline: 1.3465x; 1.0387x over previous
#include <cuda_runtime.h>
#include <math.h>

// Shapes
//   amplitudes, frequencies : [8, 250, 100] f32
//   out = concat( amp_env [8, 64000, 100], freq_env [8, 250, 100] )  f32
#define B            8
#define FRAMES       250
#define CH           100
#define CTRL_ELEMS   (B * FRAMES * CH)        // 200000
#define T_OUT        64000
#define HOP          256                      // 64000 / 250
#define ENV_ELEMS    (B * T_OUT * CH)         // 51200000
#define SEGS         (B * FRAMES)             // 2000 segments
#define SEG_VEC4     (HOP * (CH / 4))         // 6400 float4 per segment
#define UP_THREADS   800                      // 32 rows x 25 float4-groups

// ---------------------------------------------------------------------------
// Fused kernel: one block per segment (b, j).
//
// Phase 1 (200 threads): recompute get_controls for this segment and its
//   successor directly from the raw inputs into smem (no global scratch):
//     amp  = 2*sigmoid(a)^ln(10) + 1e-7, masked by (freq*harm < SR/2) + 1e-4
//     freq = 440 * 2^((sigmoid(f)*MIDI_MAX - 69)/12)
//   Block `seg` also writes its own 100 frequency outputs (each seg covered
//   exactly once). Threads 544..799 build the 256-entry hann half-window.
//
// Phase 2: thread tid owns fixed channel float4-group c4 = tid%25 and base
//   row r0 = tid/25; endpoints x0/x1 come from smem, d = x1-x0, then 8 fully
//   coalesced streaming float4 stores at rows r0 + 32k:
//     out[row] = x0 + d * w[row],  w[r] = 0.5 - 0.5*cospi(r/256)
// ---------------------------------------------------------------------------
__global__ __launch_bounds__(UP_THREADS) void synth_kernel(
        const float* __restrict__ amp_in,
        const float* __restrict__ freq_in,
        float4* __restrict__ out,
        float* __restrict__ freq_out) {
    __shared__ __align__(16) float s_x0[CH];
    __shared__ __align__(16) float s_x1[CH];
    __shared__ float sw[HOP];

    const int tid = threadIdx.x;
    const int seg = blockIdx.x;

    int segn = seg + 1;
    if (segn % FRAMES == 0) segn = seg;       // clamp: frame 250 == frame 249

    if (tid < 200) {
        const float LOG10_F  = 2.302585092994046f;   // ln(10)
        const float MIDI_MAX = 119.21309485364912f;  // 12*(log2 8000-log2 440)+69
        const float NYQ      = 22050.0f;             // SR / 2

        const int which = tid / CH;            // 0 -> seg, 1 -> segn
        const int c     = tid - which * CH;    // channel 0..99
        const int s     = which ? segn : seg;
        const int idx   = s * CH + c;

        // frequencies_sigmoid
        float f  = freq_in[idx];
        float uf = 1.0f / (1.0f + expf(-f));
        float freq = 440.0f * exp2f((uf * MIDI_MAX - 69.0f) * (1.0f / 12.0f));

        // scale_function
        float a  = amp_in[idx];
        float sa = 1.0f / (1.0f + expf(-a));
        float amp = 2.0f * powf(sa, LOG10_F) + 1e-7f;

        // remove_above_nyquist: harmonic = c+1
        float aa = ((freq * (float)(c + 1) < NYQ) ? 1.0f : 0.0f) + 1e-4f;
        float v = amp * aa;

        if (which) {
            s_x1[c] = v;
        } else {
            s_x0[c] = v;
            freq_out[idx] = freq;              // each seg written exactly once
        }
    } else if (tid >= 544) {
        const int r = tid - 544;               // 0..255
        sw[r] = 0.5f - 0.5f * cospif((float)r * (1.0f / 256.0f));
    }

    __syncthreads();

    const int c4 = tid % 25;                  // channel float4-group (fixed)
    const int r0 = tid / 25;                  // base row within segment

    const float4 x0 = *reinterpret_cast<const float4*>(&s_x0[c4 * 4]);
    const float4 x1 = *reinterpret_cast<const float4*>(&s_x1[c4 * 4]);
    float4 d;
    d.x = x1.x - x0.x;
    d.y = x1.y - x0.y;
    d.z = x1.z - x0.z;
    d.w = x1.w - x0.w;

    float4* o = out + (size_t)seg * SEG_VEC4 + tid;

#pragma unroll
    for (int k = 0; k < 8; k++) {
        const float w = sw[r0 + 32 * k];
        float4 v;
        v.x = fmaf(d.x, w, x0.x);
        v.y = fmaf(d.y, w, x0.y);
        v.z = fmaf(d.z, w, x0.z);
        v.w = fmaf(d.w, w, x0.w);
        __stcs(&o[UP_THREADS * k], v);        // streaming: write-once data
    }
}

// ---------------------------------------------------------------------------
extern "C" void kernel_launch(void* const* d_in, const int* in_sizes, int n_in,
                              void* d_out, int out_size) {
    const float* amps  = (const float*)d_in[0];
    const float* freqs = (const float*)d_in[1];
    float* out = (float*)d_out;

    synth_kernel<<<SEGS, UP_THREADS>>>(amps, freqs, (float4*)out,
                                       out + ENV_ELEMS);
}

// round 4
// speedup vs baseline: 1.3981x; 1.0383x over previous
#include <cuda_runtime.h>
#include <math.h>

// Shapes
//   amplitudes, frequencies : [8, 250, 100] f32
//   out = concat( amp_env [8, 64000, 100], freq_env [8, 250, 100] )  f32
#define B            8
#define FRAMES       250
#define CH           100
#define CTRL_ELEMS   (B * FRAMES * CH)        // 200000
#define T_OUT        64000
#define HOP          256                      // 64000 / 250
#define ENV_ELEMS    (B * T_OUT * CH)         // 51200000
#define SEGS         (B * FRAMES)             // 2000 segments
#define SEG_VEC4     (HOP * (CH / 4))         // 6400 float4 per segment
#define UP_THREADS   800                      // 32 rows x 25 float4-groups
#define GRID         296                      // 2 blocks / SM, persistent

// ---------------------------------------------------------------------------
// get_controls math for one (segment, channel) pair.
//   amp  = (2*sigmoid(a)^ln(10) + 1e-7) * ((freq*harm < SR/2) + 1e-4)
//   freq = 440 * 2^((sigmoid(f)*MIDI_MAX - 69)/12)
// ---------------------------------------------------------------------------
__device__ __forceinline__ void controls_math(float a, float f, int c,
                                              float& amp_out, float& freq_out) {
    const float LOG10_F  = 2.302585092994046f;   // ln(10)
    const float MIDI_MAX = 119.21309485364912f;  // 12*(log2 8000-log2 440)+69
    const float NYQ      = 22050.0f;             // SR / 2

    float uf   = 1.0f / (1.0f + expf(-f));
    float freq = 440.0f * exp2f((uf * MIDI_MAX - 69.0f) * (1.0f / 12.0f));

    float sa  = 1.0f / (1.0f + expf(-a));
    float amp = 2.0f * powf(sa, LOG10_F) + 1e-7f;

    float aa = ((freq * (float)(c + 1) < NYQ) ? 1.0f : 0.0f) + 1e-4f;

    amp_out  = amp * aa;
    freq_out = freq;
}

// ---------------------------------------------------------------------------
// Persistent fused kernel: 296 blocks (2/SM), each block loops over segments
// s = bid, bid+296, ... Double-buffered smem controls pipeline:
//   iter i: [issue LDGs for seg i+1] -> [8 coalesced streaming stores for
//   seg i] -> [finish controls math for i+1 into other buffer] -> barrier.
// Thread tid owns fixed channel float4-group c4 = tid%25, base row r0=tid/25;
// out[row] = x0 + (x1-x0)*w[row], w[r] = 0.5 - 0.5*cospi(r/256).
// ---------------------------------------------------------------------------
__global__ __launch_bounds__(UP_THREADS) void synth_kernel(
        const float* __restrict__ amp_in,
        const float* __restrict__ freq_in,
        float4* __restrict__ out,
        float* __restrict__ freq_out) {
    // s_amp[buf][which][c]: which=0 -> x0 (this segment), which=1 -> x1 (next)
    __shared__ __align__(16) float s_amp[2][2][CH];
    __shared__ float sw[HOP];

    const int tid = threadIdx.x;
    const int c4  = tid % 25;                 // channel float4-group (fixed)
    const int r0  = tid / 25;                 // base row within segment

    const bool ctl   = (tid < 200);
    const int  which = ctl ? (tid / CH) : 0;  // 0 -> seg, 1 -> segn
    const int  c     = ctl ? (tid - which * CH) : 0;

    // Window table (built by threads not doing controls).
    if (tid >= 544) {
        const int r = tid - 544;              // 0..255
        sw[r] = 0.5f - 0.5f * cospif((float)r * (1.0f / 256.0f));
    }

    int s   = blockIdx.x;
    int buf = 0;

    // Prologue: controls for the first segment into buf 0.
    if (ctl) {
        int ss = s + which;
        if (ss % FRAMES == 0 && which) ss = s;    // clamp at batch boundary
        const int idx = ss * CH + c;
        float amp, frq;
        controls_math(amp_in[idx], freq_in[idx], c, amp, frq);
        s_amp[0][which][c] = amp;
        if (!which) freq_out[idx] = frq;
    }
    __syncthreads();

    while (s < SEGS) {
        const int snext = s + GRID;

        // (a) Issue global loads for the NEXT segment as early as possible.
        float a_nxt = 0.0f, f_nxt = 0.0f;
        int idx_nxt = 0;
        const bool act = ctl && (snext < SEGS);
        if (act) {
            int ss = snext + which;
            if (ss % FRAMES == 0 && which) ss = snext;
            idx_nxt = ss * CH + c;
            a_nxt = amp_in[idx_nxt];
            f_nxt = freq_in[idx_nxt];
        }

        // (b) Stream the current segment's 8 coalesced float4 stores.
        const float4 x0 = *reinterpret_cast<const float4*>(&s_amp[buf][0][c4 * 4]);
        const float4 x1 = *reinterpret_cast<const float4*>(&s_amp[buf][1][c4 * 4]);
        float4 d;
        d.x = x1.x - x0.x;
        d.y = x1.y - x0.y;
        d.z = x1.z - x0.z;
        d.w = x1.w - x0.w;

        float4* o = out + (size_t)s * SEG_VEC4 + tid;
#pragma unroll
        for (int k = 0; k < 8; k++) {
            const float w = sw[r0 + 32 * k];
            float4 v;
            v.x = fmaf(d.x, w, x0.x);
            v.y = fmaf(d.y, w, x0.y);
            v.z = fmaf(d.z, w, x0.z);
            v.w = fmaf(d.w, w, x0.w);
            __stcs(&o[UP_THREADS * k], v);    // streaming: write-once data
        }

        // (c) Finish next segment's controls into the other buffer.
        if (act) {
            float amp, frq;
            controls_math(a_nxt, f_nxt, c, amp, frq);
            s_amp[buf ^ 1][which][c] = amp;
            if (!which) freq_out[idx_nxt] = frq;
        }

        // (d) One barrier per segment.
        __syncthreads();
        buf ^= 1;
        s = snext;
    }
}

// ---------------------------------------------------------------------------
extern "C" void kernel_launch(void* const* d_in, const int* in_sizes, int n_in,
                              void* d_out, int out_size) {
    const float* amps  = (const float*)d_in[0];
    const float* freqs = (const float*)d_in[1];
    float* out = (float*)d_out;

    synth_kernel<<<GRID, UP_THREADS>>>(amps, freqs, (float4*)out,
                                       out + ENV_ELEMS);
}